// round 6
// baseline (speedup 1.0000x reference)
#include <cuda_runtime.h>
#include <cuda_fp16.h>
#include <cstdint>
#include <cstddef>

// ---------------- problem dims ----------------
#define B_ 2048
#define O_ 512
#define H_ 1024
#define P_ 1024
#define C_ 512
#define T_ 12
#define BH (B_*H_)
#define BP (B_*P_)
#define BC (B_*C_)

// ---------------- GEMM tile config ----------------
#define TM 128
#define TN 128
#define TKC 64                     // k per chunk (fp16)
#define NTHREADS 256
#define STAGES 3
// A tile: [TM=128 m][TKC=64 k] fp16 (16KB); B tile: [TKC=64 k][TN=128 n] fp16 (16KB)
#define ABYTES (TM*TKC*2)
#define BBYTES (TKC*TN*2)
#define BUFBYTES (ABYTES+BBYTES)   // 32768
#define SMEM_BYTES (STAGES*BUFBYTES)

#define MODE_OH   0
#define MODE_U    1
#define MODE_STEP 2

// ---------------- device scratch (no allocs allowed) ----------------
__device__ __align__(16) __half g_in16[B_*O_];               // fp16 inputs [B][O]
__device__ __align__(16) __half g_AH16[(size_t)T_*BH];       // ah_t fp16 [T][B][H]
__device__ float  g_U[(size_t)T_*BP];                        // ah_t@w_hp + bias_p (fp32)
__device__ float  g_p[BP];
__device__ float  g_c[BC];
__device__ __align__(16) __half g_ap16A[BP];                 // fp16 ap ping-pong
__device__ __align__(16) __half g_ap16B[BP];
__device__ __align__(16) __half g_ac16A[BC];                 // fp16 ac ping-pong
__device__ __align__(16) __half g_ac16B[BC];
// fp16 weights in NATURAL [K][N] layout (no transpose; B loaded via ldmatrix.trans)
__device__ __align__(16) __half g_w16_oh[O_*H_];
__device__ __align__(16) __half g_w16_hp[H_*P_];
__device__ __align__(16) __half g_w16_pp[P_*P_];             // diag zeroed
__device__ __align__(16) __half g_w16_pc[P_*C_];
__device__ __align__(16) __half g_w16_cp[C_*P_];
// column-sum partials (8 k-segments), reduced in k_step0
__device__ float g_csp_pp0[8*P_];
__device__ float g_csp_cp[8*P_];
__device__ float g_csp_pc[8*C_];

// 1 - 0.75^t for t = 0..11
__device__ const float c_sc[T_] = {
    0.0f, 0.25f, 0.4375f, 0.578125f, 0.68359375f, 0.7626953125f,
    0.822021484375f, 0.86651611328125f, 0.8998870849609375f,
    0.92491531372070312f, 0.94368648529052734f, 0.95776486396789551f};

// ---------------- helpers ----------------
__device__ __forceinline__ uint32_t smem_u32(const void* p) {
    uint32_t a;
    asm("{ .reg .u64 t; cvta.to.shared.u64 t, %1; cvt.u32.u64 %0, t; }" : "=r"(a) : "l"(p));
    return a;
}

__device__ __forceinline__ void cpasync16(uint32_t dst, const void* src) {
    asm volatile("cp.async.cg.shared.global [%0], [%1], 16;" :: "r"(dst), "l"(src));
}

__device__ __forceinline__ void ldsm_x4(uint32_t* r, uint32_t addr) {
    asm volatile("ldmatrix.sync.aligned.m8n8.x4.shared.b16 {%0,%1,%2,%3}, [%4];"
        : "=r"(r[0]), "=r"(r[1]), "=r"(r[2]), "=r"(r[3]) : "r"(addr));
}

__device__ __forceinline__ void ldsm_x4t(uint32_t* r, uint32_t addr) {
    asm volatile("ldmatrix.sync.aligned.m8n8.x4.trans.shared.b16 {%0,%1,%2,%3}, [%4];"
        : "=r"(r[0]), "=r"(r[1]), "=r"(r[2]), "=r"(r[3]) : "r"(addr));
}

__device__ __forceinline__ void mma_f16(float* c, const uint32_t* a, const uint32_t* b) {
    asm volatile(
        "mma.sync.aligned.m16n8k16.row.col.f32.f16.f16.f32 "
        "{%0,%1,%2,%3},{%4,%5,%6,%7},{%8,%9},{%0,%1,%2,%3};"
        : "+f"(c[0]), "+f"(c[1]), "+f"(c[2]), "+f"(c[3])
        : "r"(a[0]), "r"(a[1]), "r"(a[2]), "r"(a[3]), "r"(b[0]), "r"(b[1]));
}

__device__ __forceinline__ float sigmoidf_(float x) { return 1.0f / (1.0f + __expf(-x)); }

// A tile swizzle: rows of 64 halves (8 x 16B groups), group XORed by row&7
__device__ __forceinline__ uint32_t swzA(int row, int q) {       // q = 16B group 0..7
    return (uint32_t)((row << 6) + (((q ^ row) & 7) << 3));      // in halves
}
// B tile swizzle: rows of 128 halves (16 x 16B groups); XOR low 3 bits by row&7
__device__ __forceinline__ uint32_t swzB(int row, int q) {       // q = 16B group 0..15
    return (uint32_t)((row << 7) + ((((q & 8) | ((q ^ row) & 7))) << 3));
}

// ---------------- generic fp16 mma GEMM with fused epilogues ----------------
__global__ void __launch_bounds__(NTHREADS, 2) k_gemm(
    int mode, int t,
    const float* __restrict__ bias_h,
    const float* __restrict__ bias_p,
    const float* __restrict__ bias_c,
    float* __restrict__ out)
{
    extern __shared__ __half smem[];
    const int tid = threadIdx.x, lane = tid & 31, wid = tid >> 5;
    const int wm = wid >> 1, wn = wid & 1;       // 4(m) x 2(n) warps; warp tile 32x64
    const int l7 = lane & 7;

    const __half *a0 = nullptr, *b0 = nullptr, *a1 = nullptr, *b1 = nullptr;
    int lda0 = 0, ldb0 = 0, lda1 = 0, ldb1 = 0, ch0 = 0, ch1 = 0;
    int m0 = blockIdx.x * TM;
    int n0 = 0;
    int epi = 0;  // 0=OH->AH16, 1=U store, 2=P step, 3=C step
    const __half* ap_in  = (t & 1) ? g_ap16A : g_ap16B;
    __half*       ap_out = (t & 1) ? g_ap16B : g_ap16A;
    const __half* ac_in  = (t & 1) ? g_ac16A : g_ac16B;
    __half*       ac_out = (t & 1) ? g_ac16B : g_ac16A;

    if (mode == MODE_OH) {
        n0 = blockIdx.y * TN;
        a0 = g_in16 + (size_t)m0 * O_; lda0 = O_; ch0 = O_/TKC;        // 8
        b0 = g_w16_oh + n0; ldb0 = H_;
        epi = 0;
    } else if (mode == MODE_U) {
        n0 = blockIdx.y * TN;
        a0 = g_AH16 + (size_t)m0 * H_; lda0 = H_; ch0 = H_/TKC;        // 16
        b0 = g_w16_hp + n0; ldb0 = P_;
        epi = 1;
    } else {
        if (blockIdx.y < 8) {
            n0 = blockIdx.y * TN;
            a0 = ap_in + (size_t)m0 * P_; lda0 = P_; ch0 = P_/TKC;     // 16
            b0 = g_w16_pp + n0; ldb0 = P_;
            a1 = ac_in + (size_t)m0 * C_; lda1 = C_; ch1 = C_/TKC;     // 8
            b1 = g_w16_cp + n0; ldb1 = P_;
            epi = 2;
        } else {
            n0 = (blockIdx.y - 8) * TN;
            a0 = ap_in + (size_t)m0 * P_; lda0 = P_; ch0 = P_/TKC;
            b0 = g_w16_pc + n0; ldb0 = C_;
            epi = 3;
        }
    }
    const int NC = ch0 + ch1;
    const uint32_t sbase = smem_u32(smem);

    // cooperative async load of chunk c into stage buf:
    //   A: [128 m][64 k]  B: [64 k][128 n]
    auto issue_chunk = [&](int c, int buf) {
        const __half *ga, *gb; int la, lb;
        if (c < ch0) { ga = a0 + (size_t)c*TKC;        gb = b0 + (size_t)c*TKC*ldb0;        la = lda0; lb = ldb0; }
        else         { ga = a1 + (size_t)(c-ch0)*TKC;  gb = b1 + (size_t)(c-ch0)*TKC*ldb1;  la = lda1; lb = ldb1; }
        uint32_t sA = sbase + buf*BUFBYTES;
        uint32_t sB = sA + ABYTES;
#pragma unroll
        for (int it = 0; it < 4; ++it) {          // A: 1024 16B vectors (128 rows x 8)
            int v = tid + it * NTHREADS;
            int row = v >> 3, q = v & 7;
            cpasync16(sA + swzA(row, q)*2, ga + (size_t)row*la + q*8);
        }
#pragma unroll
        for (int it = 0; it < 4; ++it) {          // B: 1024 16B vectors (64 rows x 16)
            int v = tid + it * NTHREADS;
            int row = v >> 4, q = v & 15;
            cpasync16(sB + swzB(row, q)*2, gb + (size_t)row*lb + q*8);
        }
        asm volatile("cp.async.commit_group;");
    };

    float acc[2][8][4];
#pragma unroll
    for (int mi = 0; mi < 2; mi++)
#pragma unroll
        for (int ni = 0; ni < 8; ni++)
#pragma unroll
            for (int q = 0; q < 4; q++) acc[mi][ni][q] = 0.0f;

    issue_chunk(0, 0);
    issue_chunk(1, 1);

    for (int c = 0; c < NC; ++c) {
        if (c + 1 < NC) { asm volatile("cp.async.wait_group 1;" ::: "memory"); }
        else            { asm volatile("cp.async.wait_group 0;" ::: "memory"); }
        __syncthreads();        // single barrier per chunk (issue happens post-compute)
        uint32_t sA = sbase + (c % STAGES)*BUFBYTES;
        uint32_t sB = sA + ABYTES;
#pragma unroll
        for (int ks = 0; ks < 4; ++ks) {          // k16 steps within the 64-chunk
            uint32_t af[2][4], bf[4][4];
            // A: 16m x 16k fragments (non-trans); [m][k] tile
            {
                int rbase = wm*32 + l7 + ((lane >> 3) & 1) * 8;
                int cg = ks*2 + (lane >> 4);
#pragma unroll
                for (int mi = 0; mi < 2; mi++)
                    ldsm_x4(af[mi], sA + swzA(rbase + mi*16, cg)*2);
            }
            // B: 16k x 16n fragments via ldmatrix.trans; [k][n] tile
            {
                int krow = ks*16 + (lane & 15);
#pragma unroll
                for (int j = 0; j < 4; j++) {
                    int cg = wn*8 + j*2 + (lane >> 4);
                    ldsm_x4t(bf[j], sB + swzB(krow, cg)*2);
                }
            }
#pragma unroll
            for (int mi = 0; mi < 2; mi++)
#pragma unroll
                for (int ni = 0; ni < 8; ni++)
                    mma_f16(acc[mi][ni], af[mi], bf[ni >> 1] + (ni & 1)*2);
        }
        // issue next chunk AFTER compute: its buffer's prior readers all passed
        // this iteration's __syncthreads, so no trailing barrier is needed.
        if (c + 2 < NC) issue_chunk(c + 2, (c + 2) % STAGES);
    }

    // ---------------- fused epilogue ----------------
    auto epilog2 = [&](int m, int n, float v0, float v1) {
        if (epi == 0) {
            float2 bh = *(const float2*)(bias_h + n);
            float p0 = v0 + bh.x, p1 = v1 + bh.y;
            size_t idx = (size_t)m*H_ + n;
#pragma unroll
            for (int tt = 0; tt < T_; tt++) {
                float sc = c_sc[tt];
                *(__half2*)(g_AH16 + (size_t)tt*BH + idx) =
                    __floats2half2_rn(sigmoidf_(p0*sc), sigmoidf_(p1*sc));
            }
        } else if (epi == 1) {
            float2 bp = *(const float2*)(bias_p + n);
            float2 r; r.x = v0 + bp.x; r.y = v1 + bp.y;
            *(float2*)(g_U + (size_t)m*P_ + n) = r;
        } else if (epi == 2) {
            size_t idx = (size_t)m*P_ + n;
            float2 u  = *(const float2*)(g_U + (size_t)t*BP + idx);
            float2 po = *(const float2*)(g_p + idx);
            float2 pn, s;
            pn.x = 0.25f*(v0 + u.x) + 0.75f*po.x; s.x = sigmoidf_(pn.x);
            pn.y = 0.25f*(v1 + u.y) + 0.75f*po.y; s.y = sigmoidf_(pn.y);
            *(float2*)(g_p + idx) = pn;
            *(float2*)(out + (size_t)t*BP + idx) = s;
            *(__half2*)(ap_out + idx) = __floats2half2_rn(s.x, s.y);
        } else {
            size_t idx = (size_t)m*C_ + n;
            float2 bc = *(const float2*)(bias_c + n);
            float2 co = *(const float2*)(g_c + idx);
            float2 cn, s;
            cn.x = 0.25f*(v0 + bc.x) + 0.75f*co.x; s.x = sigmoidf_(cn.x);
            cn.y = 0.25f*(v1 + bc.y) + 0.75f*co.y; s.y = sigmoidf_(cn.y);
            *(float2*)(g_c + idx) = cn;
            *(__half2*)(ac_out + idx) = __floats2half2_rn(s.x, s.y);
        }
    };

#pragma unroll
    for (int mi = 0; mi < 2; mi++) {
#pragma unroll
        for (int ni = 0; ni < 8; ni++) {
            int m = m0 + wm*32 + mi*16 + (lane >> 2);
            int n = n0 + wn*64 + ni*8 + 2*(lane & 3);
            epilog2(m,     n, acc[mi][ni][0], acc[mi][ni][1]);
            epilog2(m + 8, n, acc[mi][ni][2], acc[mi][ni][3]);
        }
    }
}

// ---------------- prep: coalesced fp16 convert (no transpose) ----------------
__global__ void k_conv(const float* __restrict__ inputs,
                       const float* __restrict__ w_oh, const float* __restrict__ w_hp,
                       const float* __restrict__ w_pp, const float* __restrict__ w_pc,
                       const float* __restrict__ w_cp) {
    int i4 = blockIdx.x * blockDim.x + threadIdx.x;
    const int S0 = B_*O_, S1 = S0 + O_*H_, S2 = S1 + H_*P_, S3 = S2 + P_*P_,
              S4 = S3 + P_*C_, S5 = S4 + C_*P_;
    int j = i4 * 4;
    if (j >= S5) return;
    const float* src; __half* dst; int rel; bool diag = false;
    if (j < S0)      { src = inputs; dst = g_in16;  rel = j; }
    else if (j < S1) { src = w_oh;   dst = g_w16_oh; rel = j - S0; }
    else if (j < S2) { src = w_hp;   dst = g_w16_hp; rel = j - S1; }
    else if (j < S3) { src = w_pp;   dst = g_w16_pp; rel = j - S2; diag = true; }
    else if (j < S4) { src = w_pc;   dst = g_w16_pc; rel = j - S3; }
    else             { src = w_cp;   dst = g_w16_cp; rel = j - S4; }
    float4 v = *(const float4*)(src + rel);
    if (diag) {
        int k = rel >> 10, nb = rel & 1023;
        if (k == nb)     v.x = 0.0f;
        if (k == nb + 1) v.y = 0.0f;
        if (k == nb + 2) v.z = 0.0f;
        if (k == nb + 3) v.w = 0.0f;
    }
    __half2 h01 = __floats2half2_rn(v.x, v.y);
    __half2 h23 = __floats2half2_rn(v.z, v.w);
    uint2 o;
    o.x = *(uint32_t*)&h01;
    o.y = *(uint32_t*)&h23;
    *(uint2*)(dst + rel) = o;
}

// ---------------- column-sum partials (coalesced, deterministic) ----------------
__global__ void k_colsum(const float* __restrict__ w_pp, const float* __restrict__ w_cp,
                         const float* __restrict__ w_pc) {
    int n = blockIdx.x * 256 + threadIdx.x;
    int seg = blockIdx.y;
    int mat = blockIdx.z;
    if (mat == 0) {                     // w_pp0 colsum: N=1024, K=1024
        int k0 = seg * 128;
        float s = 0.0f;
        for (int k = k0; k < k0 + 128; k++)
            if (k != n) s += w_pp[(size_t)k*P_ + n];
        g_csp_pp0[seg*P_ + n] = s;
    } else if (mat == 1) {              // w_cp colsum: N=1024, K=512
        int k0 = seg * 64;
        float s = 0.0f;
        for (int k = k0; k < k0 + 64; k++)
            s += w_cp[(size_t)k*P_ + n];
        g_csp_cp[seg*P_ + n] = s;
    } else {                            // w_pc colsum: N=512, K=1024
        if (n >= C_) return;
        int k0 = seg * 128;
        float s = 0.0f;
        for (int k = k0; k < k0 + 128; k++)
            s += w_pc[(size_t)k*C_ + n];
        g_csp_pc[seg*C_ + n] = s;
    }
}

// ---------------- step 0 (ap=ac=0.5 constants) ----------------
__global__ void k_step0(const float* __restrict__ bias_c, float* __restrict__ out) {
    int i = blockIdx.x * blockDim.x + threadIdx.x;
    if (i < BP) {
        int n = i & (P_ - 1);
        float cs = 0.0f;
#pragma unroll
        for (int s = 0; s < 8; s++) cs += g_csp_pp0[s*P_ + n] + g_csp_cp[s*P_ + n];
        float pn = 0.25f * (g_U[i] + 0.5f * cs);
        g_p[i] = pn;
        float sg = sigmoidf_(pn);
        out[i] = sg;
        g_ap16A[i] = __float2half(sg);     // t=1 reads g_ap16A
    } else if (i < BP + BC) {
        int j = i - BP;
        int n = j & (C_ - 1);
        float cs = 0.0f;
#pragma unroll
        for (int s = 0; s < 8; s++) cs += g_csp_pc[s*C_ + n];
        float cn = 0.25f * (0.5f * cs + bias_c[n]);
        g_c[j] = cn;
        g_ac16A[j] = __float2half(sigmoidf_(cn));   // t=1 reads g_ac16A
    }
}

// ---------------- entry point ----------------
extern "C" void kernel_launch(void* const* d_in, const int* in_sizes, int n_in,
                              void* d_out, int out_size) {
    const float* inputs = (const float*)d_in[0];
    const float* w_oh   = (const float*)d_in[1];
    const float* w_hp   = (const float*)d_in[2];
    const float* w_pp   = (const float*)d_in[3];
    const float* w_pc   = (const float*)d_in[4];
    const float* w_cp   = (const float*)d_in[5];
    const float* bias_h = (const float*)d_in[6];
    const float* bias_p = (const float*)d_in[7];
    const float* bias_c = (const float*)d_in[8];
    float* out = (float*)d_out;

    cudaFuncSetAttribute(k_gemm, cudaFuncAttributeMaxDynamicSharedMemorySize, SMEM_BYTES);

    // coalesced fp16 conversion (weights stay [K][N]; diag-zero for w_pp)
    const int TOT4 = (B_*O_ + O_*H_ + H_*P_ + P_*P_ + P_*C_ + C_*P_) / 4;
    k_conv<<<(TOT4 + 255)/256, 256>>>(inputs, w_oh, w_hp, w_pp, w_pc, w_cp);

    // column-sum partials (coalesced)
    k_colsum<<<dim3(4, 8, 3), 256>>>(w_pp, w_cp, w_pc);

    // OH GEMM: writes g_AH16 for all 12 timesteps directly
    k_gemm<<<dim3(B_/TM, H_/TN), NTHREADS, SMEM_BYTES>>>(MODE_OH, 0, bias_h, bias_p, bias_c, out);

    // U[t] = ah_t @ w_hp + bias_p  (one big M=24576 GEMM)
    k_gemm<<<dim3(T_*B_/TM, P_/TN), NTHREADS, SMEM_BYTES>>>(MODE_U, 0, bias_h, bias_p, bias_c, out);

    // step 0: ap=ac=0.5 constants -> elementwise with column sums
    k_step0<<<(BP + BC + 255)/256, 256>>>(bias_c, out);

    // steps 1..11: p-update (8 N-tiles) + c-update (4 N-tiles) in one launch
    for (int t = 1; t < T_; t++) {
        int ny = (t == T_ - 1) ? 8 : 12;   // last step: c-state never consumed
        k_gemm<<<dim3(B_/TM, ny), NTHREADS, SMEM_BYTES>>>(MODE_STEP, t, bias_h, bias_p, bias_c, out);
    }
}

// round 7
// speedup vs baseline: 1.1986x; 1.1986x over previous
#include <cuda_runtime.h>
#include <cuda_fp16.h>
#include <cstdint>
#include <cstddef>

// ---------------- problem dims ----------------
#define B_ 2048
#define O_ 512
#define H_ 1024
#define P_ 1024
#define C_ 512
#define T_ 12
#define BH (B_*H_)
#define BP (B_*P_)
#define BC (B_*C_)

// ---------------- GEMM tile config ----------------
#define TM 128
#define TN 64
#define TKC 64                     // k per chunk (fp16)
#define NTHREADS 256
#define STAGES 3
// XOR-swizzled tiles: A 128x64 fp16 (16KB, [m][k]) + B 64x64 fp16 (8KB, [k][n])
#define ABYTES (TM*TKC*2)
#define BUFBYTES ((TM+TKC)*TKC*2)  // 24576
#define SMEM_BYTES (STAGES*BUFBYTES)

#define MODE_OH   0
#define MODE_U    1
#define MODE_STEP 2

// ---------------- device scratch (no allocs allowed) ----------------
__device__ __align__(16) __half g_in16[B_*O_];               // fp16 inputs [B][O]
__device__ __align__(16) __half g_AH16[(size_t)T_*BH];       // ah_t fp16 [T][B][H]
__device__ float  g_U[(size_t)T_*BP];                        // ah_t@w_hp + bias_p (fp32)
__device__ float  g_p[BP];
__device__ float  g_c[BC];
__device__ __align__(16) __half g_ap16A[BP];                 // fp16 ap ping-pong
__device__ __align__(16) __half g_ap16B[BP];
__device__ __align__(16) __half g_ac16A[BC];                 // fp16 ac ping-pong
__device__ __align__(16) __half g_ac16B[BC];
// fp16 weights in NATURAL [K][N] layout (no transpose; B loaded via ldmatrix.trans)
__device__ __align__(16) __half g_w16_oh[O_*H_];
__device__ __align__(16) __half g_w16_hp[H_*P_];
__device__ __align__(16) __half g_w16_pp[P_*P_];             // diag zeroed
__device__ __align__(16) __half g_w16_pc[P_*C_];
__device__ __align__(16) __half g_w16_cp[C_*P_];
// column-sum partials (8 k-segments), reduced in k_step0
__device__ float g_csp_pp0[8*P_];
__device__ float g_csp_cp[8*P_];
__device__ float g_csp_pc[8*C_];

// 1 - 0.75^t for t = 0..11
__device__ const float c_sc[T_] = {
    0.0f, 0.25f, 0.4375f, 0.578125f, 0.68359375f, 0.7626953125f,
    0.822021484375f, 0.86651611328125f, 0.8998870849609375f,
    0.92491531372070312f, 0.94368648529052734f, 0.95776486396789551f};

// ---------------- helpers ----------------
__device__ __forceinline__ uint32_t smem_u32(const void* p) {
    uint32_t a;
    asm("{ .reg .u64 t; cvta.to.shared.u64 t, %1; cvt.u32.u64 %0, t; }" : "=r"(a) : "l"(p));
    return a;
}

__device__ __forceinline__ void cpasync16(uint32_t dst, const void* src) {
    asm volatile("cp.async.cg.shared.global [%0], [%1], 16;" :: "r"(dst), "l"(src));
}

__device__ __forceinline__ void ldsm_x4(uint32_t* r, uint32_t addr) {
    asm volatile("ldmatrix.sync.aligned.m8n8.x4.shared.b16 {%0,%1,%2,%3}, [%4];"
        : "=r"(r[0]), "=r"(r[1]), "=r"(r[2]), "=r"(r[3]) : "r"(addr));
}

__device__ __forceinline__ void ldsm_x4t(uint32_t* r, uint32_t addr) {
    asm volatile("ldmatrix.sync.aligned.m8n8.x4.trans.shared.b16 {%0,%1,%2,%3}, [%4];"
        : "=r"(r[0]), "=r"(r[1]), "=r"(r[2]), "=r"(r[3]) : "r"(addr));
}

__device__ __forceinline__ void mma_f16(float* c, const uint32_t* a, const uint32_t* b) {
    asm volatile(
        "mma.sync.aligned.m16n8k16.row.col.f32.f16.f16.f32 "
        "{%0,%1,%2,%3},{%4,%5,%6,%7},{%8,%9},{%0,%1,%2,%3};"
        : "+f"(c[0]), "+f"(c[1]), "+f"(c[2]), "+f"(c[3])
        : "r"(a[0]), "r"(a[1]), "r"(a[2]), "r"(a[3]), "r"(b[0]), "r"(b[1]));
}

__device__ __forceinline__ float sigmoidf_(float x) { return 1.0f / (1.0f + __expf(-x)); }

// swizzled half-offset within a tile: rows of 64 halves, 16B groups XORed by row&7
__device__ __forceinline__ uint32_t swz(int row, int qgrp) {     // qgrp = 16B group 0..7
    return (uint32_t)((row << 6) + (((qgrp ^ row) & 7) << 3));   // in halves
}

// ---------------- generic fp16 mma GEMM with fused epilogues ----------------
__global__ void __launch_bounds__(NTHREADS, 3) k_gemm(
    int mode, int t,
    const float* __restrict__ bias_h,
    const float* __restrict__ bias_p,
    const float* __restrict__ bias_c,
    float* __restrict__ out)
{
    extern __shared__ __half smem[];
    const int tid = threadIdx.x, lane = tid & 31, wid = tid >> 5;
    const int wm = wid >> 1, wn = wid & 1;       // 4(m) x 2(n) warps; warp tile 32x32
    const int l7 = lane & 7;

    const __half *a0 = nullptr, *b0 = nullptr, *a1 = nullptr, *b1 = nullptr;
    int lda0 = 0, ldb0 = 0, lda1 = 0, ldb1 = 0, ch0 = 0, ch1 = 0;
    int m0 = blockIdx.x * TM;
    int n0 = 0;
    int epi = 0;  // 0=OH->AH16, 1=U store, 2=P step, 3=C step
    const __half* ap_in  = (t & 1) ? g_ap16A : g_ap16B;
    __half*       ap_out = (t & 1) ? g_ap16B : g_ap16A;
    const __half* ac_in  = (t & 1) ? g_ac16A : g_ac16B;
    __half*       ac_out = (t & 1) ? g_ac16B : g_ac16A;

    if (mode == MODE_OH) {
        n0 = blockIdx.y * TN;
        a0 = g_in16 + (size_t)m0 * O_; lda0 = O_; ch0 = O_/TKC;        // 8
        b0 = g_w16_oh + n0; ldb0 = H_;
        epi = 0;
    } else if (mode == MODE_U) {
        n0 = blockIdx.y * TN;
        a0 = g_AH16 + (size_t)m0 * H_; lda0 = H_; ch0 = H_/TKC;        // 16
        b0 = g_w16_hp + n0; ldb0 = P_;
        epi = 1;
    } else {
        if (blockIdx.y < 16) {
            n0 = blockIdx.y * TN;
            a0 = ap_in + (size_t)m0 * P_; lda0 = P_; ch0 = P_/TKC;     // 16
            b0 = g_w16_pp + n0; ldb0 = P_;
            a1 = ac_in + (size_t)m0 * C_; lda1 = C_; ch1 = C_/TKC;     // 8
            b1 = g_w16_cp + n0; ldb1 = P_;
            epi = 2;
        } else {
            n0 = (blockIdx.y - 16) * TN;
            a0 = ap_in + (size_t)m0 * P_; lda0 = P_; ch0 = P_/TKC;
            b0 = g_w16_pc + n0; ldb0 = C_;
            epi = 3;
        }
    }
    const int NC = ch0 + ch1;
    const uint32_t sbase = smem_u32(smem);

    // cooperative async load of chunk c into stage buf:
    //   A: [TM=128 rows m][TKC=64 k]  B: [TKC=64 rows k][TN=64 n]
    auto issue_chunk = [&](int c, int buf) {
        const __half *ga, *gb; int la, lb;
        if (c < ch0) { ga = a0 + (size_t)c*TKC;        gb = b0 + (size_t)c*TKC*ldb0;        la = lda0; lb = ldb0; }
        else         { ga = a1 + (size_t)(c-ch0)*TKC;  gb = b1 + (size_t)(c-ch0)*TKC*ldb1;  la = lda1; lb = ldb1; }
        uint32_t sA = sbase + buf*BUFBYTES;
        uint32_t sB = sA + ABYTES;
#pragma unroll
        for (int it = 0; it < 4; ++it) {          // A: 1024 16B vectors
            int v = tid + it * NTHREADS;
            int row = v >> 3, q = v & 7;
            cpasync16(sA + swz(row, q)*2, ga + (size_t)row*la + q*8);
        }
#pragma unroll
        for (int it = 0; it < 2; ++it) {          // B: 512 16B vectors (k rows)
            int v = tid + it * NTHREADS;
            int row = v >> 3, q = v & 7;
            cpasync16(sB + swz(row, q)*2, gb + (size_t)row*lb + q*8);
        }
        asm volatile("cp.async.commit_group;");
    };

    float acc[2][4][4];
#pragma unroll
    for (int mi = 0; mi < 2; mi++)
#pragma unroll
        for (int ni = 0; ni < 4; ni++)
#pragma unroll
            for (int q = 0; q < 4; q++) acc[mi][ni][q] = 0.0f;

    // hoisted per-warp fragment indices (loop-invariant)
    const int a_rbase = wm*32 + l7 + ((lane >> 3) & 1) * 8;   // + mi*16
    const int a_cgoff = (lane >> 4);                          // + ks*2
    const int b_krow_l = (lane & 15);                         // + ks*16
    const int b_cg0 = wn*4 + (lane >> 4);                     // + j*2

    issue_chunk(0, 0);
    issue_chunk(1, 1);

    for (int c = 0; c < NC; ++c) {
        if (c + 1 < NC) { asm volatile("cp.async.wait_group 1;" ::: "memory"); }
        else            { asm volatile("cp.async.wait_group 0;" ::: "memory"); }
        __syncthreads();        // single barrier per chunk (issue happens post-compute)
        uint32_t sA = sbase + (c % STAGES)*BUFBYTES;
        uint32_t sB = sA + ABYTES;
#pragma unroll
        for (int ks = 0; ks < 4; ++ks) {          // k16 steps within the 64-chunk
            uint32_t af[2][4], bf[2][4];
            // A: 16m x 16k fragments (non-trans); [m][k] tile
            {
                int cg = ks*2 + a_cgoff;
#pragma unroll
                for (int mi = 0; mi < 2; mi++)
                    ldsm_x4(af[mi], sA + swz(a_rbase + mi*16, cg)*2);
            }
            // B: 16k x 16n fragments via ldmatrix.trans; [k][n] tile
            {
                int krow = ks*16 + b_krow_l;
#pragma unroll
                for (int j = 0; j < 2; j++)
                    ldsm_x4t(bf[j], sB + swz(krow, b_cg0 + j*2)*2);
            }
#pragma unroll
            for (int mi = 0; mi < 2; mi++)
#pragma unroll
                for (int ni = 0; ni < 4; ni++)
                    mma_f16(acc[mi][ni], af[mi], bf[ni >> 1] + (ni & 1)*2);
        }
        // issue next chunk AFTER compute: buffer (c+2)%3's previous readers all
        // passed this iteration's top __syncthreads, so no trailing barrier needed.
        if (c + 2 < NC) issue_chunk(c + 2, (c + 2) % STAGES);
    }

    // ---------------- fused epilogue ----------------
    auto epilog2 = [&](int m, int n, float v0, float v1) {
        if (epi == 0) {
            float2 bh = *(const float2*)(bias_h + n);
            float p0 = v0 + bh.x, p1 = v1 + bh.y;
            size_t idx = (size_t)m*H_ + n;
#pragma unroll
            for (int tt = 0; tt < T_; tt++) {
                float sc = c_sc[tt];
                *(__half2*)(g_AH16 + (size_t)tt*BH + idx) =
                    __floats2half2_rn(sigmoidf_(p0*sc), sigmoidf_(p1*sc));
            }
        } else if (epi == 1) {
            float2 bp = *(const float2*)(bias_p + n);
            float2 r; r.x = v0 + bp.x; r.y = v1 + bp.y;
            *(float2*)(g_U + (size_t)m*P_ + n) = r;
        } else if (epi == 2) {
            size_t idx = (size_t)m*P_ + n;
            float2 u  = *(const float2*)(g_U + (size_t)t*BP + idx);
            float2 po = *(const float2*)(g_p + idx);
            float2 pn, s;
            pn.x = 0.25f*(v0 + u.x) + 0.75f*po.x; s.x = sigmoidf_(pn.x);
            pn.y = 0.25f*(v1 + u.y) + 0.75f*po.y; s.y = sigmoidf_(pn.y);
            *(float2*)(g_p + idx) = pn;
            *(float2*)(out + (size_t)t*BP + idx) = s;
            *(__half2*)(ap_out + idx) = __floats2half2_rn(s.x, s.y);
        } else {
            size_t idx = (size_t)m*C_ + n;
            float2 bc = *(const float2*)(bias_c + n);
            float2 co = *(const float2*)(g_c + idx);
            float2 cn, s;
            cn.x = 0.25f*(v0 + bc.x) + 0.75f*co.x; s.x = sigmoidf_(cn.x);
            cn.y = 0.25f*(v1 + bc.y) + 0.75f*co.y; s.y = sigmoidf_(cn.y);
            *(float2*)(g_c + idx) = cn;
            *(__half2*)(ac_out + idx) = __floats2half2_rn(s.x, s.y);
        }
    };

#pragma unroll
    for (int mi = 0; mi < 2; mi++) {
#pragma unroll
        for (int ni = 0; ni < 4; ni++) {
            int m = m0 + wm*32 + mi*16 + (lane >> 2);
            int n = n0 + wn*32 + ni*8 + 2*(lane & 3);
            epilog2(m,     n, acc[mi][ni][0], acc[mi][ni][1]);
            epilog2(m + 8, n, acc[mi][ni][2], acc[mi][ni][3]);
        }
    }
}

// ---------------- prep: coalesced fp16 convert (no transpose) ----------------
__global__ void k_conv(const float* __restrict__ inputs,
                       const float* __restrict__ w_oh, const float* __restrict__ w_hp,
                       const float* __restrict__ w_pp, const float* __restrict__ w_pc,
                       const float* __restrict__ w_cp) {
    int i4 = blockIdx.x * blockDim.x + threadIdx.x;
    const int S0 = B_*O_, S1 = S0 + O_*H_, S2 = S1 + H_*P_, S3 = S2 + P_*P_,
              S4 = S3 + P_*C_, S5 = S4 + C_*P_;
    int j = i4 * 4;
    if (j >= S5) return;
    const float* src; __half* dst; int rel; bool diag = false;
    if (j < S0)      { src = inputs; dst = g_in16;  rel = j; }
    else if (j < S1) { src = w_oh;   dst = g_w16_oh; rel = j - S0; }
    else if (j < S2) { src = w_hp;   dst = g_w16_hp; rel = j - S1; }
    else if (j < S3) { src = w_pp;   dst = g_w16_pp; rel = j - S2; diag = true; }
    else if (j < S4) { src = w_pc;   dst = g_w16_pc; rel = j - S3; }
    else             { src = w_cp;   dst = g_w16_cp; rel = j - S4; }
    float4 v = *(const float4*)(src + rel);
    if (diag) {
        int k = rel >> 10, nb = rel & 1023;
        if (k == nb)     v.x = 0.0f;
        if (k == nb + 1) v.y = 0.0f;
        if (k == nb + 2) v.z = 0.0f;
        if (k == nb + 3) v.w = 0.0f;
    }
    __half2 h01 = __floats2half2_rn(v.x, v.y);
    __half2 h23 = __floats2half2_rn(v.z, v.w);
    uint2 o;
    o.x = *(uint32_t*)&h01;
    o.y = *(uint32_t*)&h23;
    *(uint2*)(dst + rel) = o;
}

// ---------------- column-sum partials (coalesced, deterministic) ----------------
__global__ void k_colsum(const float* __restrict__ w_pp, const float* __restrict__ w_cp,
                         const float* __restrict__ w_pc) {
    int n = blockIdx.x * 256 + threadIdx.x;
    int seg = blockIdx.y;
    int mat = blockIdx.z;
    if (mat == 0) {                     // w_pp0 colsum: N=1024, K=1024
        int k0 = seg * 128;
        float s = 0.0f;
        for (int k = k0; k < k0 + 128; k++)
            if (k != n) s += w_pp[(size_t)k*P_ + n];
        g_csp_pp0[seg*P_ + n] = s;
    } else if (mat == 1) {              // w_cp colsum: N=1024, K=512
        int k0 = seg * 64;
        float s = 0.0f;
        for (int k = k0; k < k0 + 64; k++)
            s += w_cp[(size_t)k*P_ + n];
        g_csp_cp[seg*P_ + n] = s;
    } else {                            // w_pc colsum: N=512, K=1024
        if (n >= C_) return;
        int k0 = seg * 128;
        float s = 0.0f;
        for (int k = k0; k < k0 + 128; k++)
            s += w_pc[(size_t)k*C_ + n];
        g_csp_pc[seg*C_ + n] = s;
    }
}

// ---------------- step 0 (ap=ac=0.5 constants) ----------------
__global__ void k_step0(const float* __restrict__ bias_c, float* __restrict__ out) {
    int i = blockIdx.x * blockDim.x + threadIdx.x;
    if (i < BP) {
        int n = i & (P_ - 1);
        float cs = 0.0f;
#pragma unroll
        for (int s = 0; s < 8; s++) cs += g_csp_pp0[s*P_ + n] + g_csp_cp[s*P_ + n];
        float pn = 0.25f * (g_U[i] + 0.5f * cs);
        g_p[i] = pn;
        float sg = sigmoidf_(pn);
        out[i] = sg;
        g_ap16A[i] = __float2half(sg);     // t=1 reads g_ap16A
    } else if (i < BP + BC) {
        int j = i - BP;
        int n = j & (C_ - 1);
        float cs = 0.0f;
#pragma unroll
        for (int s = 0; s < 8; s++) cs += g_csp_pc[s*C_ + n];
        float cn = 0.25f * (0.5f * cs + bias_c[n]);
        g_c[j] = cn;
        g_ac16A[j] = __float2half(sigmoidf_(cn));   // t=1 reads g_ac16A
    }
}

// ---------------- entry point ----------------
extern "C" void kernel_launch(void* const* d_in, const int* in_sizes, int n_in,
                              void* d_out, int out_size) {
    const float* inputs = (const float*)d_in[0];
    const float* w_oh   = (const float*)d_in[1];
    const float* w_hp   = (const float*)d_in[2];
    const float* w_pp   = (const float*)d_in[3];
    const float* w_pc   = (const float*)d_in[4];
    const float* w_cp   = (const float*)d_in[5];
    const float* bias_h = (const float*)d_in[6];
    const float* bias_p = (const float*)d_in[7];
    const float* bias_c = (const float*)d_in[8];
    float* out = (float*)d_out;

    cudaFuncSetAttribute(k_gemm, cudaFuncAttributeMaxDynamicSharedMemorySize, SMEM_BYTES);

    // coalesced fp16 conversion (weights stay [K][N]; diag-zero for w_pp)
    const int TOT4 = (B_*O_ + O_*H_ + H_*P_ + P_*P_ + P_*C_ + C_*P_) / 4;
    k_conv<<<(TOT4 + 255)/256, 256>>>(inputs, w_oh, w_hp, w_pp, w_pc, w_cp);

    // column-sum partials (coalesced)
    k_colsum<<<dim3(4, 8, 3), 256>>>(w_pp, w_cp, w_pc);

    // OH GEMM: writes g_AH16 for all 12 timesteps directly
    k_gemm<<<dim3(B_/TM, H_/TN), NTHREADS, SMEM_BYTES>>>(MODE_OH, 0, bias_h, bias_p, bias_c, out);

    // U[t] = ah_t @ w_hp + bias_p  (one big M=24576 GEMM)
    k_gemm<<<dim3(T_*B_/TM, P_/TN), NTHREADS, SMEM_BYTES>>>(MODE_U, 0, bias_h, bias_p, bias_c, out);

    // step 0: ap=ac=0.5 constants -> elementwise with column sums
    k_step0<<<(BP + BC + 255)/256, 256>>>(bias_c, out);

    // steps 1..11: p-update (16 N-tiles) + c-update (8 N-tiles) in one launch
    for (int t = 1; t < T_; t++) {
        int ny = (t == T_ - 1) ? 16 : 24;   // last step: c-state never consumed
        k_gemm<<<dim3(B_/TM, ny), NTHREADS, SMEM_BYTES>>>(MODE_STEP, t, bias_h, bias_p, bias_c, out);
    }
}